// round 6
// baseline (speedup 1.0000x reference)
#include <cuda_runtime.h>
#include <math.h>

#define V      100000
#define E      1000000
#define D      200
#define R      474
#define HALF   500000
#define CAP    96        // edge-bucket capacity per node (Poisson(10); max deg ~30)
#define NPB    16        // nodes per block in main kernel
#define NPG    8         // nodes per thread-group
#define PAD    20        // transposed xs row stride (floats)
#define TPB    448       // 2 groups x 224 threads; o = t%224, active o<200

// ---------------- device scratch (no runtime allocation allowed) ------------
__device__ float    g_Mtab[2 * R * D];        // softmax(rel @ W)/3
__device__ float    g_Weff[D * D];            // 160KB, L1-resident
__device__ int      g_cnt[V];
__device__ uint2    g_edge[(size_t)V * CAP];  // bucketed: {key, float_bits(norm)}
__device__ float    g_stats[2 * D];           // colsum, colsumsq

__device__ __forceinline__ void fma2(unsigned long long& acc,
                                     unsigned long long a,
                                     unsigned long long b) {
    asm("fma.rn.f32x2 %0, %1, %2, %0;" : "+l"(acc) : "l"(a), "l"(b));
}

// ---------------- launch 0: zero counters + stats ----------------------------
__global__ void k_zero() {
    int i = blockIdx.x * blockDim.x + threadIdx.x;
    if (i < V) g_cnt[i] = 0;
    if (i < 2 * D) g_stats[i] = 0.f;
}

// ---------------- launch 1: mtab + weff + relout ------------------------------
// blocks [0,948): message table; [948,1148): Weff; [1148,1622): rel_out
__global__ void k_pre(const float* __restrict__ rel,
                      const float* __restrict__ in_w,
                      const float* __restrict__ out_w,
                      const float* __restrict__ loop_rel,
                      const float* __restrict__ loop_w,
                      const float* __restrict__ w_rel,
                      float* __restrict__ out2) {
    int b = blockIdx.x, t = threadIdx.x;
    if (b < 2 * R) {
        // softmax(rel_repr[r] @ W) / 3
        __shared__ float rr[D];
        __shared__ float red[256];
        int s = b / R, r = b % R;
        const float* W = s ? out_w : in_w;
        for (int i = t; i < D; i += 256) rr[i] = rel[r * D + i];
        __syncthreads();
        float dot = 0.f;
        if (t < D) {
            #pragma unroll 4
            for (int j = 0; j < D; j++) dot += rr[j] * W[j * D + t];
        }
        red[t] = (t < D) ? dot : -INFINITY;
        __syncthreads();
        for (int ofs = 128; ofs > 0; ofs >>= 1) {
            if (t < ofs) red[t] = fmaxf(red[t], red[t + ofs]);
            __syncthreads();
        }
        float mx = red[0];
        __syncthreads();
        float e = (t < D) ? expf(dot - mx) : 0.f;
        red[t] = e;
        __syncthreads();
        for (int ofs = 128; ofs > 0; ofs >>= 1) {
            if (t < ofs) red[t] += red[t + ofs];
            __syncthreads();
        }
        float inv = (1.f / 3.f) / red[0];
        if (t < D) g_Mtab[(s * R + r) * D + t] = e * inv;
    } else if (b < 2 * R + D) {
        // W_eff[j,o] = sum_k loop_rel[(j+k)%D] * loop_w[k,o], /3
        __shared__ float lr[D];
        int j = b - 2 * R;
        for (int i = t; i < D; i += 256) lr[i] = loop_rel[i];
        __syncthreads();
        if (t < D) {
            float a = 0.f;
            int jj = j;
            #pragma unroll 4
            for (int k = 0; k < D; k++) {
                a += lr[jj] * loop_w[k * D + t];
                jj++; if (jj == D) jj = 0;
            }
            g_Weff[j * D + t] = a * (1.f / 3.f);
        }
    } else {
        // rel_out = rel_repr @ w_rel
        __shared__ float rr[D];
        int r = b - (2 * R + D);
        for (int i = t; i < D; i += 256) rr[i] = rel[r * D + i];
        __syncthreads();
        if (t < D) {
            float a = 0.f;
            #pragma unroll 4
            for (int j = 0; j < D; j++) a += rr[j] * w_rel[j * D + t];
            out2[r * D + t] = a;
        }
    }
}

// ---------------- launch 2: direct bucket scatter (no CSR) -------------------
__global__ void k_scatter(const int* __restrict__ dst,
                          const int* __restrict__ et,
                          const float* __restrict__ norm) {
    int i = blockIdx.x * blockDim.x + threadIdx.x;
    if (i < E) {
        int v = dst[i];
        int p = atomicAdd(&g_cnt[v], 1);
        if (p < CAP) {
            uint2 rec;
            rec.x = (unsigned)et[i] + ((i >= HALF) ? R : 0);
            rec.y = __float_as_uint(norm[i]);
            g_edge[(size_t)v * CAP + p] = rec;
        }
    }
}

// ---------------- launch 3: fused gather-agg + x@Weff + stats ----------------
// 2 thread-groups per block: group g handles nodes [8g, 8g+8) of the 16-node tile.
__global__ void __launch_bounds__(TPB) k_main(const float* __restrict__ x,
                                              const float* __restrict__ bias,
                                              float* __restrict__ out) {
    __shared__ float xs[D * PAD];   // transposed: xs[j*PAD + n]
    int t  = threadIdx.x;
    int g  = t / 224;               // group 0 or 1
    int o  = t % 224;               // feature id, active if < 200
    int v0 = blockIdx.x * NPB;
    int nb = g * NPG;               // node base within tile

    for (int i = t; i < NPB * D; i += TPB) {
        int n = i / D, j = i % D;
        xs[j * PAD + n] = x[(v0 + n) * D + j];
    }
    __syncthreads();

    if (o < D) {
        // ---- edge aggregation for this group's 8 nodes (bucketed, MLP-4) ----
        float ea[NPG];
        #pragma unroll 1
        for (int n = 0; n < NPG; n++) {
            int vtx = v0 + nb + n;
            int cnt = g_cnt[vtx];
            if (cnt > CAP) cnt = CAP;
            const uint2* eb = &g_edge[(size_t)vtx * CAP];
            float a = 0.f;
            int e = 0;
            for (; e + 4 <= cnt; e += 4) {
                uint2 r0 = eb[e],     r1 = eb[e + 1];
                uint2 r2 = eb[e + 2], r3 = eb[e + 3];
                float m0 = g_Mtab[(int)r0.x * D + o];
                float m1 = g_Mtab[(int)r1.x * D + o];
                float m2 = g_Mtab[(int)r2.x * D + o];
                float m3 = g_Mtab[(int)r3.x * D + o];
                a += __uint_as_float(r0.y) * m0 + __uint_as_float(r1.y) * m1;
                a += __uint_as_float(r2.y) * m2 + __uint_as_float(r3.y) * m3;
            }
            for (; e < cnt; e++) {
                uint2 r = eb[e];
                a += __uint_as_float(r.y) * g_Mtab[(int)r.x * D + o];
            }
            ea[n] = a;
        }

        // ---- seed node-pair packed accumulators (4 x 64-bit) ----
        unsigned long long acc2[NPG / 2];
        #pragma unroll
        for (int k = 0; k < NPG / 2; k++) {
            asm("mov.b64 %0, {%1, %2};"
                : "=l"(acc2[k]) : "f"(ea[2 * k]), "f"(ea[2 * k + 1]));
        }

        // ---- GEMM: acc += x @ Weff (L1-resident weights, f32x2) ----
        #pragma unroll 2
        for (int jp = 0; jp < D / 2; jp++) {
            int j0 = 2 * jp;
            float w0 = g_Weff[j0 * D + o];
            float w1 = g_Weff[(j0 + 1) * D + o];
            unsigned long long wd0, wd1;
            asm("mov.b64 %0, {%1, %1};" : "=l"(wd0) : "f"(w0));
            asm("mov.b64 %0, {%1, %1};" : "=l"(wd1) : "f"(w1));
            const longlong2* xr0 = (const longlong2*)&xs[j0 * PAD + nb];
            const longlong2* xr1 = (const longlong2*)&xs[(j0 + 1) * PAD + nb];
            longlong2 a = *xr0;
            fma2(acc2[0], (unsigned long long)a.x, wd0);
            fma2(acc2[1], (unsigned long long)a.y, wd0);
            longlong2 b2 = xr0[1];
            fma2(acc2[2], (unsigned long long)b2.x, wd0);
            fma2(acc2[3], (unsigned long long)b2.y, wd0);
            longlong2 c = *xr1;
            fma2(acc2[0], (unsigned long long)c.x, wd1);
            fma2(acc2[1], (unsigned long long)c.y, wd1);
            longlong2 d = xr1[1];
            fma2(acc2[2], (unsigned long long)d.x, wd1);
            fma2(acc2[3], (unsigned long long)d.y, wd1);
        }

        // ---- epilogue: unpack, bias, store, stats ----
        float b = bias[o];
        float lsum = 0.f, lsq = 0.f;
        #pragma unroll
        for (int k = 0; k < NPG / 2; k++) {
            float a0, a1;
            asm("mov.b64 {%0, %1}, %2;" : "=f"(a0), "=f"(a1) : "l"(acc2[k]));
            float p0 = a0 + b;
            float p1 = a1 + b;
            out[(v0 + nb + 2 * k) * D + o]     = p0;
            out[(v0 + nb + 2 * k + 1) * D + o] = p1;
            lsum += p0 + p1;
            lsq  += p0 * p0 + p1 * p1;
        }
        atomicAdd(&g_stats[o], lsum);
        atomicAdd(&g_stats[D + o], lsq);
    }
}

// ---------------- launch 4: BN finalize (per-block) + normalize ---------------
__global__ void k_norm(const float* __restrict__ bnw,
                       const float* __restrict__ bnb,
                       float* __restrict__ out) {
    __shared__ float sc[D], sh[D];
    int t = threadIdx.x;
    for (int i = t; i < D; i += blockDim.x) {
        float mean = g_stats[i] * (1.f / (float)V);
        float var  = g_stats[D + i] * (1.f / (float)V) - mean * mean;
        float s    = bnw[i] * rsqrtf(var + 1e-5f);
        sc[i] = s;
        sh[i] = bnb[i] - mean * s;
    }
    __syncthreads();
    const int n4 = V * D / 4;
    for (int i = blockIdx.x * blockDim.x + t; i < n4; i += gridDim.x * blockDim.x) {
        float4 v = ((float4*)out)[i];
        int o = (i * 4) % D;
        v.x = v.x * sc[o]     + sh[o];
        v.y = v.y * sc[o + 1] + sh[o + 1];
        v.z = v.z * sc[o + 2] + sh[o + 2];
        v.w = v.w * sc[o + 3] + sh[o + 3];
        ((float4*)out)[i] = v;
    }
}

// ---------------- launch ----------------------------------------------------
extern "C" void kernel_launch(void* const* d_in, const int* in_sizes, int n_in,
                              void* d_out, int out_size) {
    const float* x        = (const float*)d_in[0];
    const float* rel      = (const float*)d_in[1];
    const float* enorm    = (const float*)d_in[2];
    const float* in_w     = (const float*)d_in[3];
    const float* out_w    = (const float*)d_in[4];
    const float* loop_w   = (const float*)d_in[5];
    const float* w_rel    = (const float*)d_in[6];
    const float* loop_rel = (const float*)d_in[7];
    const float* bias     = (const float*)d_in[8];
    const float* bnw      = (const float*)d_in[9];
    const float* bnb      = (const float*)d_in[10];
    const int*   et       = (const int*)d_in[11];
    const int*   dst      = (const int*)d_in[12];
    float*       out      = (float*)d_out;

    k_zero<<<(V + 255) / 256, 256>>>();                                  // 0
    k_pre<<<2 * R + D + R, 256>>>(rel, in_w, out_w, loop_rel, loop_w,
                                  w_rel, out + (size_t)V * D);           // 1
    k_scatter<<<(E + 255) / 256, 256>>>(dst, et, enorm);                 // 2
    k_main<<<V / NPB, TPB>>>(x, bias, out);                              // 3  <- ncu
    k_norm<<<2048, 256>>>(bnw, bnb, out);                                // 4
}

// round 8
// speedup vs baseline: 1.0868x; 1.0868x over previous
#include <cuda_runtime.h>
#include <cuda_bf16.h>
#include <math.h>
#include <stdint.h>

#define V      100000
#define E      1000000
#define D      200
#define R      474
#define HALF   500000
#define NBLK   98        // ceil(V/1024) for scan
#define NG     6250      // node groups of 16 (V = 6250*16 exactly)
#define NKT    13        // k-tiles of 16 (K padded 200 -> 208)
#define NNT    25        // n-tiles of 8  (D = 25*8 exactly)

// ---------------- device scratch (no runtime allocation allowed) ------------
__device__ float g_Mtab[2 * R * D];               // softmax(rel @ W)/3
__device__ uint4 g_Ahi[(size_t)NG * NKT * 32];    // x hi, mma A-fragment order
__device__ uint4 g_Alo[(size_t)NG * NKT * 32];    // x lo
__device__ uint2 g_Bhi[NKT * NNT * 32];           // Weff hi, B-fragment order
__device__ uint2 g_Blo[NKT * NNT * 32];           // Weff lo (pads never written = 0)
__device__ int   g_cnt[V];
__device__ int   g_off[V + 1];
__device__ int   g_cur[V];
__device__ uint2 g_edge[E];                       // CSR {key, norm bits}
__device__ int   g_bsum[128];
__device__ float g_stats[2 * D];                  // colsum, colsumsq

// mma.sync m16n8k16 row.col f32.bf16.bf16.f32 — base PTX, compiles on compute_103
#define MMA(c, a, b) \
    asm volatile("mma.sync.aligned.m16n8k16.row.col.f32.bf16.bf16.f32 " \
                 "{%0,%1,%2,%3}, {%4,%5,%6,%7}, {%8,%9}, {%0,%1,%2,%3};" \
                 : "+f"((c)[0]), "+f"((c)[1]), "+f"((c)[2]), "+f"((c)[3]) \
                 : "r"((a).x), "r"((a).y), "r"((a).z), "r"((a).w), \
                   "r"((b).x), "r"((b).y))

// ---------------- launch 0: zero counters + stats ----------------------------
__global__ void k_zero() {
    int i = blockIdx.x * blockDim.x + threadIdx.x;
    if (i < V) g_cnt[i] = 0;
    if (i < D) { g_stats[i] = 0.f; g_stats[D + i] = 0.f; }
}

// ---------------- launch 1: mtab + Weff (B-fragments, bf16 split) + relout ---
__global__ void k_pre(const float* __restrict__ rel,
                      const float* __restrict__ in_w,
                      const float* __restrict__ out_w,
                      const float* __restrict__ loop_rel,
                      const float* __restrict__ loop_w,
                      const float* __restrict__ w_rel,
                      float* __restrict__ out2) {
    int b = blockIdx.x, t = threadIdx.x;
    if (b < 2 * R) {
        // softmax(rel_repr[r] @ W) / 3
        __shared__ float rr[D];
        __shared__ float red[256];
        int s = b / R, r = b % R;
        const float* W = s ? out_w : in_w;
        for (int i = t; i < D; i += 256) rr[i] = rel[r * D + i];
        __syncthreads();
        float dot = 0.f;
        if (t < D) {
            #pragma unroll 4
            for (int j = 0; j < D; j++) dot += rr[j] * W[j * D + t];
        }
        red[t] = (t < D) ? dot : -INFINITY;
        __syncthreads();
        for (int ofs = 128; ofs > 0; ofs >>= 1) {
            if (t < ofs) red[t] = fmaxf(red[t], red[t + ofs]);
            __syncthreads();
        }
        float mx = red[0];
        __syncthreads();
        float e = (t < D) ? expf(dot - mx) : 0.f;
        red[t] = e;
        __syncthreads();
        for (int ofs = 128; ofs > 0; ofs >>= 1) {
            if (t < ofs) red[t] += red[t + ofs];
            __syncthreads();
        }
        float inv = (1.f / 3.f) / red[0];
        if (t < D) g_Mtab[(s * R + r) * D + t] = e * inv;
    } else if (b < 2 * R + D) {
        // W_eff[j,t] = sum_k loop_rel[(j+k)%D]*loop_w[k,t] / 3,
        // written straight into mma B-fragment slots (k=j, n=t).
        __shared__ float lr[D];
        int j = b - 2 * R;
        for (int i = t; i < D; i += 256) lr[i] = loop_rel[i];
        __syncthreads();
        if (t < D) {
            float a = 0.f;
            int jj = j;
            #pragma unroll 4
            for (int k = 0; k < D; k++) {
                a += lr[jj] * loop_w[k * D + t];
                jj++; if (jj == D) jj = 0;
            }
            a *= (1.f / 3.f);
            __nv_bfloat16 h = __float2bfloat16(a);
            __nv_bfloat16 l = __float2bfloat16(a - __bfloat162float(h));
            // B frag: b_reg = r>>3, lane = (n%8)*4 + ((r&7)>>1), half = r&1
            int kt = j >> 4, rr2 = j & 15;
            int nt = t >> 3, gg = t & 7;
            int lane = gg * 4 + ((rr2 & 7) >> 1);
            int reg = rr2 >> 3, half = rr2 & 1;
            size_t bi = ((((size_t)(kt * NNT + nt) * 32 + lane) * 2 + reg) * 2 + half);
            ((__nv_bfloat16*)g_Bhi)[bi] = h;
            ((__nv_bfloat16*)g_Blo)[bi] = l;
        }
    } else {
        // rel_out = rel_repr @ w_rel
        __shared__ float rr[D];
        int r = b - (2 * R + D);
        for (int i = t; i < D; i += 256) rr[i] = rel[r * D + i];
        __syncthreads();
        if (t < D) {
            float a = 0.f;
            #pragma unroll 4
            for (int j = 0; j < D; j++) a += rr[j] * w_rel[j * D + t];
            out2[r * D + t] = a;
        }
    }
}

// ---------------- launch 2: x -> split-bf16 A fragments ----------------------
// thread i -> (group, ktile, lane); writes one uint4 {a0,a1,a2,a3} per array.
__global__ void k_cvt(const float* __restrict__ x) {
    int i = blockIdx.x * 256 + threadIdx.x;
    if (i >= NG * NKT * 32) return;
    int lane = i & 31;
    int kt   = (i >> 5) % NKT;
    int grp  = i / (NKT * 32);
    int g  = lane >> 2;
    int c0 = kt * 16 + (lane & 3) * 2;        // cols c0,c0+1 and c0+8,c0+9
    const float* xr0 = x + (size_t)(grp * 16 + g) * D;
    const float* xr1 = xr0 + 8 * D;
    bool ok8 = (c0 + 8 < D);                  // only false for kt == 12
    float2 p00 = *(const float2*)(xr0 + c0);
    float2 p10 = *(const float2*)(xr1 + c0);
    float2 p01 = ok8 ? *(const float2*)(xr0 + c0 + 8) : make_float2(0.f, 0.f);
    float2 p11 = ok8 ? *(const float2*)(xr1 + c0 + 8) : make_float2(0.f, 0.f);

    uint4 ah, al;
    {
        __nv_bfloat162 h = __floats2bfloat162_rn(p00.x, p00.y);
        __nv_bfloat162 l = __floats2bfloat162_rn(p00.x - __bfloat162float(h.x),
                                                 p00.y - __bfloat162float(h.y));
        ah.x = *(uint32_t*)&h; al.x = *(uint32_t*)&l;
    }
    {
        __nv_bfloat162 h = __floats2bfloat162_rn(p10.x, p10.y);
        __nv_bfloat162 l = __floats2bfloat162_rn(p10.x - __bfloat162float(h.x),
                                                 p10.y - __bfloat162float(h.y));
        ah.y = *(uint32_t*)&h; al.y = *(uint32_t*)&l;
    }
    {
        __nv_bfloat162 h = __floats2bfloat162_rn(p01.x, p01.y);
        __nv_bfloat162 l = __floats2bfloat162_rn(p01.x - __bfloat162float(h.x),
                                                 p01.y - __bfloat162float(h.y));
        ah.z = *(uint32_t*)&h; al.z = *(uint32_t*)&l;
    }
    {
        __nv_bfloat162 h = __floats2bfloat162_rn(p11.x, p11.y);
        __nv_bfloat162 l = __floats2bfloat162_rn(p11.x - __bfloat162float(h.x),
                                                 p11.y - __bfloat162float(h.y));
        ah.w = *(uint32_t*)&h; al.w = *(uint32_t*)&l;
    }
    g_Ahi[i] = ah;
    g_Alo[i] = al;
}

// ---------------- launch 3: mma.sync GEMM  out = x @ Weff + bias -------------
// Grid NG, 5 warps/block. Warp w: ntiles [5w, 5w+5). Split-bf16: 3 MMAs/tile.
__global__ void __launch_bounds__(160) k_gemm(const float* __restrict__ bias,
                                              float* __restrict__ out) {
    int w = threadIdx.x >> 5, lane = threadIdx.x & 31;
    int grp = blockIdx.x;
    float acc[5][4] = {};

    const uint4* Ah = g_Ahi + (size_t)grp * NKT * 32 + lane;
    const uint4* Al = g_Alo + (size_t)grp * NKT * 32 + lane;
    #pragma unroll 1
    for (int kt = 0; kt < NKT; kt++) {
        uint4 ah = Ah[kt * 32];
        uint4 al = Al[kt * 32];
        #pragma unroll
        for (int nt = 0; nt < 5; nt++) {
            int gnt = w * 5 + nt;
            uint2 bh = g_Bhi[(kt * NNT + gnt) * 32 + lane];
            uint2 bl = g_Blo[(kt * NNT + gnt) * 32 + lane];
            MMA(acc[nt], ah, bh);   // hi * Whi
            MMA(acc[nt], al, bh);   // lo * Whi
            MMA(acc[nt], ah, bl);   // hi * Wlo
        }
    }

    // epilogue: D frag -> out, plus bias
    int g  = lane >> 2, t2 = (lane & 3) * 2;
    size_t r0 = (size_t)(grp * 16 + g) * D;
    size_t r1 = r0 + 8 * D;
    #pragma unroll
    for (int nt = 0; nt < 5; nt++) {
        int col = (w * 5 + nt) * 8 + t2;
        float b0 = bias[col], b1 = bias[col + 1];
        float2 v01 = make_float2(acc[nt][0] + b0, acc[nt][1] + b1);
        float2 v23 = make_float2(acc[nt][2] + b0, acc[nt][3] + b1);
        *(float2*)&out[r0 + col] = v01;
        *(float2*)&out[r1 + col] = v23;
    }
}

// ---------------- CSR build: hist -> scan -> scatter -------------------------
__global__ void k_hist(const int* __restrict__ dst) {
    int i = blockIdx.x * blockDim.x + threadIdx.x;
    if (i < E) atomicAdd(&g_cnt[dst[i]], 1);
}

__global__ void k_scan1() {
    __shared__ int sh[256];
    int b = blockIdx.x, t = threadIdx.x;
    int base = b * 1024 + t * 4;
    int s = 0;
    #pragma unroll
    for (int i = 0; i < 4; i++) {
        int v = base + i;
        if (v < V) s += g_cnt[v];
    }
    sh[t] = s;
    __syncthreads();
    for (int ofs = 128; ofs > 0; ofs >>= 1) {
        if (t < ofs) sh[t] += sh[t + ofs];
        __syncthreads();
    }
    if (t == 0) g_bsum[b] = sh[0];
}

__global__ void k_scan3m() {
    __shared__ int sh[256];
    __shared__ int bs[128];
    __shared__ int bpre;
    int b = blockIdx.x, t = threadIdx.x;
    if (t < NBLK) bs[t] = g_bsum[t];
    __syncthreads();
    if (t == 0) {
        int run = 0;
        for (int i = 0; i < b; i++) run += bs[i];
        bpre = run;
        if (b == NBLK - 1) g_off[V] = E;
    }
    int base = b * 1024 + t * 4;
    int c[4];
    int local = 0;
    #pragma unroll
    for (int i = 0; i < 4; i++) {
        int v = base + i;
        c[i] = (v < V) ? g_cnt[v] : 0;
        local += c[i];
    }
    sh[t] = local;
    __syncthreads();
    for (int ofs = 1; ofs < 256; ofs <<= 1) {
        int val = 0;
        if (t >= ofs) val = sh[t - ofs];
        __syncthreads();
        sh[t] += val;
        __syncthreads();
    }
    int excl = sh[t] - local + bpre;
    #pragma unroll
    for (int i = 0; i < 4; i++) {
        int v = base + i;
        if (v < V) { g_off[v] = excl; g_cur[v] = excl; }
        excl += c[i];
    }
}

__global__ void k_scatter(const int* __restrict__ dst,
                          const int* __restrict__ et,
                          const float* __restrict__ norm) {
    int i = blockIdx.x * blockDim.x + threadIdx.x;
    if (i < E) {
        int v = dst[i];
        int p = atomicAdd(&g_cur[v], 1);
        uint2 rec;
        rec.x = (unsigned)et[i] + ((i >= HALF) ? R : 0);
        rec.y = __float_as_uint(norm[i]);
        g_edge[p] = rec;
    }
}

// ---------------- launch 8: edge aggregation, RMW into out -------------------
__global__ void __launch_bounds__(448) k_edge(float* __restrict__ out) {
    int t = threadIdx.x;
    int g = t / 224, o = t % 224;
    int v0 = blockIdx.x * 16 + g * 8;
    if (o < D) {
        #pragma unroll 1
        for (int n = 0; n < 8; n++) {
            int vtx = v0 + n;
            int e  = g_off[vtx];
            int t2 = g_off[vtx + 1];
            float a = 0.f;
            for (; e + 4 <= t2; e += 4) {
                uint2 r0 = g_edge[e],     r1 = g_edge[e + 1];
                uint2 r2 = g_edge[e + 2], r3 = g_edge[e + 3];
                float m0 = g_Mtab[(int)r0.x * D + o];
                float m1 = g_Mtab[(int)r1.x * D + o];
                float m2 = g_Mtab[(int)r2.x * D + o];
                float m3 = g_Mtab[(int)r3.x * D + o];
                a += __uint_as_float(r0.y) * m0 + __uint_as_float(r1.y) * m1;
                a += __uint_as_float(r2.y) * m2 + __uint_as_float(r3.y) * m3;
            }
            for (; e < t2; e++) {
                uint2 r = g_edge[e];
                a += __uint_as_float(r.y) * g_Mtab[(int)r.x * D + o];
            }
            out[(size_t)vtx * D + o] += a;
        }
    }
}

// ---------------- launch 9: column stats (fixed-col striding) ----------------
__global__ void k_stats(const float* __restrict__ out) {
    int g = blockIdx.x * 256 + threadIdx.x;      // 51200 threads; 51200 % 50 == 0
    const float4* o4 = (const float4*)out;
    float s0 = 0, s1 = 0, s2 = 0, s3 = 0;
    float q0 = 0, q1 = 0, q2 = 0, q3 = 0;
    for (int i = g; i < V * 50; i += 51200) {
        float4 v = o4[i];
        s0 += v.x; q0 += v.x * v.x;
        s1 += v.y; q1 += v.y * v.y;
        s2 += v.z; q2 += v.z * v.z;
        s3 += v.w; q3 += v.w * v.w;
    }
    int c = (g % 50) * 4;
    atomicAdd(&g_stats[c],     s0);  atomicAdd(&g_stats[c + 1],     s1);
    atomicAdd(&g_stats[c + 2], s2);  atomicAdd(&g_stats[c + 3],     s3);
    atomicAdd(&g_stats[D + c],     q0);  atomicAdd(&g_stats[D + c + 1], q1);
    atomicAdd(&g_stats[D + c + 2], q2);  atomicAdd(&g_stats[D + c + 3], q3);
}

// ---------------- launch 10: BN finalize + normalize -------------------------
__global__ void k_norm(const float* __restrict__ bnw,
                       const float* __restrict__ bnb,
                       float* __restrict__ out) {
    __shared__ float sc[D], sh[D];
    int t = threadIdx.x;
    for (int i = t; i < D; i += blockDim.x) {
        float mean = g_stats[i] * (1.f / (float)V);
        float var  = g_stats[D + i] * (1.f / (float)V) - mean * mean;
        float s    = bnw[i] * rsqrtf(var + 1e-5f);
        sc[i] = s;
        sh[i] = bnb[i] - mean * s;
    }
    __syncthreads();
    const int n4 = V * D / 4;
    for (int i = blockIdx.x * blockDim.x + t; i < n4; i += gridDim.x * blockDim.x) {
        float4 v = ((float4*)out)[i];
        int o = (i * 4) % D;
        v.x = v.x * sc[o]     + sh[o];
        v.y = v.y * sc[o + 1] + sh[o + 1];
        v.z = v.z * sc[o + 2] + sh[o + 2];
        v.w = v.w * sc[o + 3] + sh[o + 3];
        ((float4*)out)[i] = v;
    }
}

// ---------------- launch ----------------------------------------------------
extern "C" void kernel_launch(void* const* d_in, const int* in_sizes, int n_in,
                              void* d_out, int out_size) {
    const float* x        = (const float*)d_in[0];
    const float* rel      = (const float*)d_in[1];
    const float* enorm    = (const float*)d_in[2];
    const float* in_w     = (const float*)d_in[3];
    const float* out_w    = (const float*)d_in[4];
    const float* loop_w   = (const float*)d_in[5];
    const float* w_rel    = (const float*)d_in[6];
    const float* loop_rel = (const float*)d_in[7];
    const float* bias     = (const float*)d_in[8];
    const float* bnw      = (const float*)d_in[9];
    const float* bnb      = (const float*)d_in[10];
    const int*   et       = (const int*)d_in[11];
    const int*   dst      = (const int*)d_in[12];
    float*       out      = (float*)d_out;

    k_zero<<<(V + 255) / 256, 256>>>();                                  // 0
    k_pre<<<2 * R + D + R, 256>>>(rel, in_w, out_w, loop_rel, loop_w,
                                  w_rel, out + (size_t)V * D);           // 1
    k_cvt<<<(NG * NKT * 32 + 255) / 256, 256>>>(x);                      // 2
    k_gemm<<<NG, 160>>>(bias, out);                                      // 3 <- ncu
    k_hist<<<(E + 255) / 256, 256>>>(dst);                               // 4
    k_scan1<<<NBLK, 256>>>();                                            // 5
    k_scan3m<<<NBLK, 256>>>();                                           // 6
    k_scatter<<<(E + 255) / 256, 256>>>(dst, et, enorm);                 // 7
    k_edge<<<V / 16, 448>>>(out);                                        // 8
    k_stats<<<200, 256>>>(out);                                          // 9
    k_norm<<<2048, 256>>>(bnw, bnb, out);                                // 10
}

// round 9
// speedup vs baseline: 1.7887x; 1.6459x over previous
#include <cuda_runtime.h>
#include <cuda_bf16.h>
#include <math.h>
#include <stdint.h>

#define V      100000
#define E      1000000
#define D      200
#define R      474
#define HALF   500000
#define NBLK   98        // ceil(V/1024) for scan
#define NKT    13        // k-tiles of 16 (K 200 -> 208 logical)
#define NNT    25        // n-tiles of 8  (D = 25*8)
#define GPB    2         // 16-row A groups per block -> 32 rows/block
#define NGB    3125      // V / 32

// ---------------- device scratch (no runtime allocation allowed) ------------
__device__ float g_Mtab[2 * R * D];        // softmax(rel @ W)/3
__device__ uint2 g_Bhi[NKT * NNT * 32];    // Weff hi, B-fragment order
__device__ uint2 g_Blo[NKT * NNT * 32];    // Weff lo (pad slots never written = 0)
__device__ int   g_cnt[V];
__device__ int   g_off[V + 1];
__device__ int   g_cur[V];
__device__ uint2 g_edge[E];                // CSR {key, norm bits}
__device__ int   g_bsum[128];
__device__ float g_stats[2 * D];           // colsum, colsumsq

#define MMA(c, a, b) \
    asm volatile("mma.sync.aligned.m16n8k16.row.col.f32.bf16.bf16.f32 " \
                 "{%0,%1,%2,%3}, {%4,%5,%6,%7}, {%8,%9}, {%0,%1,%2,%3};" \
                 : "+f"((c)[0]), "+f"((c)[1]), "+f"((c)[2]), "+f"((c)[3]) \
                 : "r"((a)[0]), "r"((a)[1]), "r"((a)[2]), "r"((a)[3]), \
                   "r"((b).x), "r"((b).y))

__device__ __forceinline__ void cvt2(float2 p, uint32_t& hi, uint32_t& lo) {
    __nv_bfloat162 h = __floats2bfloat162_rn(p.x, p.y);
    __nv_bfloat162 l = __floats2bfloat162_rn(p.x - __bfloat162float(h.x),
                                             p.y - __bfloat162float(h.y));
    hi = *(uint32_t*)&h;
    lo = *(uint32_t*)&l;
}

// ---------------- launch 0: zero counters + stats ----------------------------
__global__ void k_zero() {
    int i = blockIdx.x * blockDim.x + threadIdx.x;
    if (i < V) g_cnt[i] = 0;
    if (i < D) { g_stats[i] = 0.f; g_stats[D + i] = 0.f; }
}

// ---------------- launch 1: mtab + Weff (B-fragments, split) + relout --------
__global__ void k_pre(const float* __restrict__ rel,
                      const float* __restrict__ in_w,
                      const float* __restrict__ out_w,
                      const float* __restrict__ loop_rel,
                      const float* __restrict__ loop_w,
                      const float* __restrict__ w_rel,
                      float* __restrict__ out2) {
    int b = blockIdx.x, t = threadIdx.x;
    if (b < 2 * R) {
        __shared__ float rr[D];
        __shared__ float red[256];
        int s = b / R, r = b % R;
        const float* W = s ? out_w : in_w;
        for (int i = t; i < D; i += 256) rr[i] = rel[r * D + i];
        __syncthreads();
        float dot = 0.f;
        if (t < D) {
            #pragma unroll 4
            for (int j = 0; j < D; j++) dot += rr[j] * W[j * D + t];
        }
        red[t] = (t < D) ? dot : -INFINITY;
        __syncthreads();
        for (int ofs = 128; ofs > 0; ofs >>= 1) {
            if (t < ofs) red[t] = fmaxf(red[t], red[t + ofs]);
            __syncthreads();
        }
        float mx = red[0];
        __syncthreads();
        float e = (t < D) ? expf(dot - mx) : 0.f;
        red[t] = e;
        __syncthreads();
        for (int ofs = 128; ofs > 0; ofs >>= 1) {
            if (t < ofs) red[t] += red[t + ofs];
            __syncthreads();
        }
        float inv = (1.f / 3.f) / red[0];
        if (t < D) g_Mtab[(s * R + r) * D + t] = e * inv;
    } else if (b < 2 * R + D) {
        // W_eff[j,t] -> mma B-fragment slots (k=j, n=t), bf16 split
        __shared__ float lr[D];
        int j = b - 2 * R;
        for (int i = t; i < D; i += 256) lr[i] = loop_rel[i];
        __syncthreads();
        if (t < D) {
            float a = 0.f;
            int jj = j;
            #pragma unroll 4
            for (int k = 0; k < D; k++) {
                a += lr[jj] * loop_w[k * D + t];
                jj++; if (jj == D) jj = 0;
            }
            a *= (1.f / 3.f);
            __nv_bfloat16 h = __float2bfloat16(a);
            __nv_bfloat16 l = __float2bfloat16(a - __bfloat162float(h));
            int kt = j >> 4, rr2 = j & 15;
            int nt = t >> 3, gg = t & 7;
            int lane = gg * 4 + ((rr2 & 7) >> 1);
            int reg = rr2 >> 3, half = rr2 & 1;
            size_t bi = ((((size_t)(kt * NNT + nt) * 32 + lane) * 2 + reg) * 2 + half);
            ((__nv_bfloat16*)g_Bhi)[bi] = h;
            ((__nv_bfloat16*)g_Blo)[bi] = l;
        }
    } else {
        __shared__ float rr[D];
        int r = b - (2 * R + D);
        for (int i = t; i < D; i += 256) rr[i] = rel[r * D + i];
        __syncthreads();
        if (t < D) {
            float a = 0.f;
            #pragma unroll 4
            for (int j = 0; j < D; j++) a += rr[j] * w_rel[j * D + t];
            out2[r * D + t] = a;
        }
    }
}

// ---------------- launch 2: histogram ----------------------------------------
__global__ void k_hist(const int* __restrict__ dst) {
    int i = blockIdx.x * blockDim.x + threadIdx.x;
    if (i < E) atomicAdd(&g_cnt[dst[i]], 1);
}

// ---------------- launch 3: fused cvt + mma GEMM  out = x @ Weff + bias ------
// Grid NGB, 5 warps. Block: 32 rows (2 A groups). Warp w: ntiles [5w,5w+5).
// A fragments built in-register from fp32 x (L1-shared across the 5 warps).
__global__ void __launch_bounds__(160) k_gemm(const float* __restrict__ x,
                                              const float* __restrict__ bias,
                                              float* __restrict__ out) {
    int w = threadIdx.x >> 5, lane = threadIdx.x & 31;
    int v0 = blockIdx.x * (GPB * 16);
    float acc[GPB][5][4] = {};

    int gr = lane >> 2;                    // fragment row 0..7
    int cbase = (lane & 3) * 2;            // col pair offset in tile

    #pragma unroll 1
    for (int kt = 0; kt < NKT; kt++) {
        int c0 = kt * 16 + cbase;
        bool ok8 = (c0 + 8 < D);           // kt==12 upper half is pad
        uint32_t ah[GPB][4], al[GPB][4];
        #pragma unroll
        for (int g = 0; g < GPB; g++) {
            const float* xr0 = x + (size_t)(v0 + g * 16 + gr) * D;
            const float* xr1 = xr0 + 8 * D;
            float2 p00 = *(const float2*)(xr0 + c0);
            float2 p10 = *(const float2*)(xr1 + c0);
            float2 p01 = ok8 ? *(const float2*)(xr0 + c0 + 8) : make_float2(0.f, 0.f);
            float2 p11 = ok8 ? *(const float2*)(xr1 + c0 + 8) : make_float2(0.f, 0.f);
            cvt2(p00, ah[g][0], al[g][0]);
            cvt2(p10, ah[g][1], al[g][1]);
            cvt2(p01, ah[g][2], al[g][2]);
            cvt2(p11, ah[g][3], al[g][3]);
        }
        #pragma unroll
        for (int nt = 0; nt < 5; nt++) {
            int gnt = w * 5 + nt;
            uint2 bh = g_Bhi[(kt * NNT + gnt) * 32 + lane];
            uint2 bl = g_Blo[(kt * NNT + gnt) * 32 + lane];
            #pragma unroll
            for (int g = 0; g < GPB; g++) {
                MMA(acc[g][nt], ah[g], bh);   // hi * Whi
                MMA(acc[g][nt], al[g], bh);   // lo * Whi
                MMA(acc[g][nt], ah[g], bl);   // hi * Wlo
            }
        }
    }

    // epilogue: D frag -> out, plus bias
    #pragma unroll
    for (int g = 0; g < GPB; g++) {
        size_t r0 = (size_t)(v0 + g * 16 + gr) * D;
        size_t r1 = r0 + 8 * D;
        #pragma unroll
        for (int nt = 0; nt < 5; nt++) {
            int col = (w * 5 + nt) * 8 + cbase;
            float b0 = bias[col], b1 = bias[col + 1];
            *(float2*)&out[r0 + col] =
                make_float2(acc[g][nt][0] + b0, acc[g][nt][1] + b1);
            *(float2*)&out[r1 + col] =
                make_float2(acc[g][nt][2] + b0, acc[g][nt][3] + b1);
        }
    }
}

// ---------------- CSR scan + scatter -----------------------------------------
__global__ void k_scan1() {
    __shared__ int sh[256];
    int b = blockIdx.x, t = threadIdx.x;
    int base = b * 1024 + t * 4;
    int s = 0;
    #pragma unroll
    for (int i = 0; i < 4; i++) {
        int v = base + i;
        if (v < V) s += g_cnt[v];
    }
    sh[t] = s;
    __syncthreads();
    for (int ofs = 128; ofs > 0; ofs >>= 1) {
        if (t < ofs) sh[t] += sh[t + ofs];
        __syncthreads();
    }
    if (t == 0) g_bsum[b] = sh[0];
}

__global__ void k_scan3m() {
    __shared__ int sh[256];
    __shared__ int bs[128];
    __shared__ int bpre;
    int b = blockIdx.x, t = threadIdx.x;
    if (t < NBLK) bs[t] = g_bsum[t];
    __syncthreads();
    if (t == 0) {
        int run = 0;
        for (int i = 0; i < b; i++) run += bs[i];
        bpre = run;
        if (b == NBLK - 1) g_off[V] = E;
    }
    int base = b * 1024 + t * 4;
    int c[4];
    int local = 0;
    #pragma unroll
    for (int i = 0; i < 4; i++) {
        int v = base + i;
        c[i] = (v < V) ? g_cnt[v] : 0;
        local += c[i];
    }
    sh[t] = local;
    __syncthreads();
    for (int ofs = 1; ofs < 256; ofs <<= 1) {
        int val = 0;
        if (t >= ofs) val = sh[t - ofs];
        __syncthreads();
        sh[t] += val;
        __syncthreads();
    }
    int excl = sh[t] - local + bpre;
    #pragma unroll
    for (int i = 0; i < 4; i++) {
        int v = base + i;
        if (v < V) { g_off[v] = excl; g_cur[v] = excl; }
        excl += c[i];
    }
}

__global__ void k_scatter(const int* __restrict__ dst,
                          const int* __restrict__ et,
                          const float* __restrict__ norm) {
    int i = blockIdx.x * blockDim.x + threadIdx.x;
    if (i < E) {
        int v = dst[i];
        int p = atomicAdd(&g_cur[v], 1);
        uint2 rec;
        rec.x = (unsigned)et[i] + ((i >= HALF) ? R : 0);
        rec.y = __float_as_uint(norm[i]);
        g_edge[p] = rec;
    }
}

// ---------------- launch 7: edge aggregation + stats, RMW into out -----------
__global__ void __launch_bounds__(448) k_edge(float* __restrict__ out) {
    int t = threadIdx.x;
    int g = t / 224, o = t % 224;
    int v0 = blockIdx.x * 16 + g * 8;
    if (o < D) {
        float lsum = 0.f, lsq = 0.f;
        #pragma unroll 1
        for (int n = 0; n < 8; n++) {
            int vtx = v0 + n;
            int e  = g_off[vtx];
            int t2 = g_off[vtx + 1];
            float a = 0.f;
            for (; e + 4 <= t2; e += 4) {
                uint2 r0 = g_edge[e],     r1 = g_edge[e + 1];
                uint2 r2 = g_edge[e + 2], r3 = g_edge[e + 3];
                float m0 = g_Mtab[(int)r0.x * D + o];
                float m1 = g_Mtab[(int)r1.x * D + o];
                float m2 = g_Mtab[(int)r2.x * D + o];
                float m3 = g_Mtab[(int)r3.x * D + o];
                a += __uint_as_float(r0.y) * m0 + __uint_as_float(r1.y) * m1;
                a += __uint_as_float(r2.y) * m2 + __uint_as_float(r3.y) * m3;
            }
            for (; e < t2; e++) {
                uint2 r = g_edge[e];
                a += __uint_as_float(r.y) * g_Mtab[(int)r.x * D + o];
            }
            size_t idx = (size_t)vtx * D + o;
            float p = out[idx] + a;
            out[idx] = p;
            lsum += p;
            lsq  += p * p;
        }
        atomicAdd(&g_stats[o], lsum);
        atomicAdd(&g_stats[D + o], lsq);
    }
}

// ---------------- launch 8: BN finalize + normalize --------------------------
__global__ void k_norm(const float* __restrict__ bnw,
                       const float* __restrict__ bnb,
                       float* __restrict__ out) {
    __shared__ float sc[D], sh[D];
    int t = threadIdx.x;
    for (int i = t; i < D; i += blockDim.x) {
        float mean = g_stats[i] * (1.f / (float)V);
        float var  = g_stats[D + i] * (1.f / (float)V) - mean * mean;
        float s    = bnw[i] * rsqrtf(var + 1e-5f);
        sc[i] = s;
        sh[i] = bnb[i] - mean * s;
    }
    __syncthreads();
    const int n4 = V * D / 4;
    for (int i = blockIdx.x * blockDim.x + t; i < n4; i += gridDim.x * blockDim.x) {
        float4 v = ((float4*)out)[i];
        int o = (i * 4) % D;
        v.x = v.x * sc[o]     + sh[o];
        v.y = v.y * sc[o + 1] + sh[o + 1];
        v.z = v.z * sc[o + 2] + sh[o + 2];
        v.w = v.w * sc[o + 3] + sh[o + 3];
        ((float4*)out)[i] = v;
    }
}

// ---------------- launch ----------------------------------------------------
extern "C" void kernel_launch(void* const* d_in, const int* in_sizes, int n_in,
                              void* d_out, int out_size) {
    const float* x        = (const float*)d_in[0];
    const float* rel      = (const float*)d_in[1];
    const float* enorm    = (const float*)d_in[2];
    const float* in_w     = (const float*)d_in[3];
    const float* out_w    = (const float*)d_in[4];
    const float* loop_w   = (const float*)d_in[5];
    const float* w_rel    = (const float*)d_in[6];
    const float* loop_rel = (const float*)d_in[7];
    const float* bias     = (const float*)d_in[8];
    const float* bnw      = (const float*)d_in[9];
    const float* bnb      = (const float*)d_in[10];
    const int*   et       = (const int*)d_in[11];
    const int*   dst      = (const int*)d_in[12];
    float*       out      = (float*)d_out;

    k_zero<<<(V + 255) / 256, 256>>>();                                  // 0
    k_pre<<<2 * R + D + R, 256>>>(rel, in_w, out_w, loop_rel, loop_w,
                                  w_rel, out + (size_t)V * D);           // 1
    k_hist<<<(E + 255) / 256, 256>>>(dst);                               // 2
    k_gemm<<<NGB, 160>>>(x, bias, out);                                  // 3 <- ncu
    k_scan1<<<NBLK, 256>>>();                                            // 4
    k_scan3m<<<NBLK, 256>>>();                                           // 5
    k_scatter<<<(E + 255) / 256, 256>>>(dst, et, enorm);                 // 6
    k_edge<<<V / 16, 448>>>(out);                                        // 7
    k_norm<<<2048, 256>>>(bnw, bnb, out);                                // 8
}

// round 10
// speedup vs baseline: 1.8003x; 1.0065x over previous
#include <cuda_runtime.h>
#include <cuda_bf16.h>
#include <math.h>
#include <stdint.h>

#define V      100000
#define E      1000000
#define D      200
#define R      474
#define HALF   500000
#define NBLK   98        // ceil(V/1024) for scan
#define NKT    13        // k-tiles of 16 (K 200 -> 208 logical)
#define NNT    25        // n-tiles of 8  (D = 25*8)
#define GPB    2         // 16-row A groups per block -> 32 rows/block
#define NGB    3125      // V / 32

// ---------------- device scratch (no runtime allocation allowed) ------------
__device__ float g_Mtab[2 * R * D];        // softmax(rel @ W)/3
__device__ uint2 g_Bhi[NKT * NNT * 32];    // Weff hi, B-fragment order
__device__ uint2 g_Blo[NKT * NNT * 32];    // Weff lo (pad slots never written = 0)
__device__ int   g_cnt[V];
__device__ int   g_off[V + 1];
__device__ int   g_cur[V];
__device__ uint2 g_edge[E];                // CSR {key, norm bits}
__device__ int   g_bsum[128];
__device__ float g_stats[2 * D];           // colsum, colsumsq

#define MMA(c, a, b) \
    asm volatile("mma.sync.aligned.m16n8k16.row.col.f32.bf16.bf16.f32 " \
                 "{%0,%1,%2,%3}, {%4,%5,%6,%7}, {%8,%9}, {%0,%1,%2,%3};" \
                 : "+f"((c)[0]), "+f"((c)[1]), "+f"((c)[2]), "+f"((c)[3]) \
                 : "r"((a)[0]), "r"((a)[1]), "r"((a)[2]), "r"((a)[3]), \
                   "r"((b).x), "r"((b).y))

__device__ __forceinline__ void cvt2(float2 p, uint32_t& hi, uint32_t& lo) {
    __nv_bfloat162 h = __floats2bfloat162_rn(p.x, p.y);
    __nv_bfloat162 l = __floats2bfloat162_rn(p.x - __bfloat162float(h.x),
                                             p.y - __bfloat162float(h.y));
    hi = *(uint32_t*)&h;
    lo = *(uint32_t*)&l;
}

// load + split-convert one kt's A fragments for both row-groups
__device__ __forceinline__ void loadcvt(const float* __restrict__ x,
                                        int v0, int gr, int cbase, int kt,
                                        uint32_t ah[GPB][4], uint32_t al[GPB][4]) {
    int c0 = kt * 16 + cbase;
    bool ok8 = (c0 + 8 < D);                  // kt==12 upper half is pad
    #pragma unroll
    for (int g = 0; g < GPB; g++) {
        const float* xr0 = x + (size_t)(v0 + g * 16 + gr) * D;
        const float* xr1 = xr0 + 8 * D;
        float2 p00 = *(const float2*)(xr0 + c0);
        float2 p10 = *(const float2*)(xr1 + c0);
        float2 p01 = ok8 ? *(const float2*)(xr0 + c0 + 8) : make_float2(0.f, 0.f);
        float2 p11 = ok8 ? *(const float2*)(xr1 + c0 + 8) : make_float2(0.f, 0.f);
        cvt2(p00, ah[g][0], al[g][0]);
        cvt2(p10, ah[g][1], al[g][1]);
        cvt2(p01, ah[g][2], al[g][2]);
        cvt2(p11, ah[g][3], al[g][3]);
    }
}

// all MMAs for one kt (B fragments loaded here; L1/L2-resident table)
__device__ __forceinline__ void domma(int w, int lane, int kt,
                                      uint32_t ah[GPB][4], uint32_t al[GPB][4],
                                      float acc[GPB][5][4]) {
    #pragma unroll
    for (int nt = 0; nt < 5; nt++) {
        int gnt = w * 5 + nt;
        uint2 bh = g_Bhi[(kt * NNT + gnt) * 32 + lane];
        uint2 bl = g_Blo[(kt * NNT + gnt) * 32 + lane];
        #pragma unroll
        for (int g = 0; g < GPB; g++) {
            MMA(acc[g][nt], ah[g], bh);   // hi * Whi
            MMA(acc[g][nt], al[g], bh);   // lo * Whi
            MMA(acc[g][nt], ah[g], bl);   // hi * Wlo
        }
    }
}

// ---------------- launch 0: mtab + Weff + relout + zero ----------------------
// blocks: [0,948) mtab; [948,1148) Weff; [1148,1622) relout; [1622,1721) zero
__global__ void k_pre(const float* __restrict__ rel,
                      const float* __restrict__ in_w,
                      const float* __restrict__ out_w,
                      const float* __restrict__ loop_rel,
                      const float* __restrict__ loop_w,
                      const float* __restrict__ w_rel,
                      float* __restrict__ out2) {
    int b = blockIdx.x, t = threadIdx.x;
    if (b < 2 * R) {
        __shared__ float rr[D];
        __shared__ float red[256];
        int s = b / R, r = b % R;
        const float* W = s ? out_w : in_w;
        for (int i = t; i < D; i += 256) rr[i] = rel[r * D + i];
        __syncthreads();
        float dot = 0.f;
        if (t < D) {
            #pragma unroll 4
            for (int j = 0; j < D; j++) dot += rr[j] * W[j * D + t];
        }
        red[t] = (t < D) ? dot : -INFINITY;
        __syncthreads();
        for (int ofs = 128; ofs > 0; ofs >>= 1) {
            if (t < ofs) red[t] = fmaxf(red[t], red[t + ofs]);
            __syncthreads();
        }
        float mx = red[0];
        __syncthreads();
        float e = (t < D) ? expf(dot - mx) : 0.f;
        red[t] = e;
        __syncthreads();
        for (int ofs = 128; ofs > 0; ofs >>= 1) {
            if (t < ofs) red[t] += red[t + ofs];
            __syncthreads();
        }
        float inv = (1.f / 3.f) / red[0];
        if (t < D) g_Mtab[(s * R + r) * D + t] = e * inv;
    } else if (b < 2 * R + D) {
        // W_eff[j,t] -> mma B-fragment slots (k=j, n=t), bf16 split
        __shared__ float lr[D];
        int j = b - 2 * R;
        for (int i = t; i < D; i += 256) lr[i] = loop_rel[i];
        __syncthreads();
        if (t < D) {
            float a = 0.f;
            int jj = j;
            #pragma unroll 4
            for (int k = 0; k < D; k++) {
                a += lr[jj] * loop_w[k * D + t];
                jj++; if (jj == D) jj = 0;
            }
            a *= (1.f / 3.f);
            __nv_bfloat16 h = __float2bfloat16(a);
            __nv_bfloat16 l = __float2bfloat16(a - __bfloat162float(h));
            int kt = j >> 4, rr2 = j & 15;
            int nt = t >> 3, gg = t & 7;
            int lane = gg * 4 + ((rr2 & 7) >> 1);
            int reg = rr2 >> 3, half = rr2 & 1;
            size_t bi = ((((size_t)(kt * NNT + nt) * 32 + lane) * 2 + reg) * 2 + half);
            ((__nv_bfloat16*)g_Bhi)[bi] = h;
            ((__nv_bfloat16*)g_Blo)[bi] = l;
        }
    } else if (b < 2 * R + D + R) {
        __shared__ float rr[D];
        int r = b - (2 * R + D);
        for (int i = t; i < D; i += 256) rr[i] = rel[r * D + i];
        __syncthreads();
        if (t < D) {
            float a = 0.f;
            #pragma unroll 4
            for (int j = 0; j < D; j++) a += rr[j] * w_rel[j * D + t];
            out2[r * D + t] = a;
        }
    } else {
        // zero counters + stats
        int zb = b - (2 * R + D + R);
        int base = zb * 1024 + t * 4;
        #pragma unroll
        for (int i = 0; i < 4; i++) {
            int v = base + i;
            if (v < V) g_cnt[v] = 0;
        }
        if (zb == 0 && t < D) { g_stats[t] = 0.f; g_stats[D + t] = 0.f; }
    }
}

// ---------------- launch 1: histogram ----------------------------------------
__global__ void k_hist(const int* __restrict__ dst) {
    int i = blockIdx.x * blockDim.x + threadIdx.x;
    if (i < E) atomicAdd(&g_cnt[dst[i]], 1);
}

// ---------------- launch 2: per-superblock degree sums -----------------------
__global__ void k_scan1() {
    __shared__ int sh[256];
    int b = blockIdx.x, t = threadIdx.x;
    int base = b * 1024 + t * 4;
    int s = 0;
    #pragma unroll
    for (int i = 0; i < 4; i++) {
        int v = base + i;
        if (v < V) s += g_cnt[v];
    }
    sh[t] = s;
    __syncthreads();
    for (int ofs = 128; ofs > 0; ofs >>= 1) {
        if (t < ofs) sh[t] += sh[t + ofs];
        __syncthreads();
    }
    if (t == 0) g_bsum[b] = sh[0];
}

// ---------------- launch 3: pipelined cvt + mma GEMM -------------------------
// Grid NGB, 5 warps. Block: 32 rows. Warp w: ntiles [5w,5w+5).
// 2-stage software pipeline: A fragments for kt+1 load during kt's MMAs.
__global__ void __launch_bounds__(160) k_gemm(const float* __restrict__ x,
                                              const float* __restrict__ bias,
                                              float* __restrict__ out) {
    int w = threadIdx.x >> 5, lane = threadIdx.x & 31;
    int v0 = blockIdx.x * (GPB * 16);
    int gr = lane >> 2;                    // fragment row 0..7
    int cbase = (lane & 3) * 2;            // col pair offset in tile
    float acc[GPB][5][4] = {};

    uint32_t ahA[GPB][4], alA[GPB][4];
    uint32_t ahB[GPB][4], alB[GPB][4];

    loadcvt(x, v0, gr, cbase, 0, ahA, alA);
    #pragma unroll 1
    for (int k2 = 0; k2 < 6; k2++) {
        loadcvt(x, v0, gr, cbase, 2 * k2 + 1, ahB, alB);
        domma(w, lane, 2 * k2, ahA, alA, acc);
        loadcvt(x, v0, gr, cbase, 2 * k2 + 2, ahA, alA);
        domma(w, lane, 2 * k2 + 1, ahB, alB, acc);
    }
    domma(w, lane, 12, ahA, alA, acc);

    // epilogue: D frag -> out, plus bias
    #pragma unroll
    for (int g = 0; g < GPB; g++) {
        size_t r0 = (size_t)(v0 + g * 16 + gr) * D;
        size_t r1 = r0 + 8 * D;
        #pragma unroll
        for (int nt = 0; nt < 5; nt++) {
            int col = (w * 5 + nt) * 8 + cbase;
            float b0 = bias[col], b1 = bias[col + 1];
            *(float2*)&out[r0 + col] =
                make_float2(acc[g][nt][0] + b0, acc[g][nt][1] + b1);
            *(float2*)&out[r1 + col] =
                make_float2(acc[g][nt][2] + b0, acc[g][nt][3] + b1);
        }
    }
}

// ---------------- launch 4: offsets from block prefix ------------------------
__global__ void k_scan3m() {
    __shared__ int sh[256];
    __shared__ int bs[128];
    __shared__ int bpre;
    int b = blockIdx.x, t = threadIdx.x;
    if (t < NBLK) bs[t] = g_bsum[t];
    __syncthreads();
    if (t == 0) {
        int run = 0;
        for (int i = 0; i < b; i++) run += bs[i];
        bpre = run;
        if (b == NBLK - 1) g_off[V] = E;
    }
    int base = b * 1024 + t * 4;
    int c[4];
    int local = 0;
    #pragma unroll
    for (int i = 0; i < 4; i++) {
        int v = base + i;
        c[i] = (v < V) ? g_cnt[v] : 0;
        local += c[i];
    }
    sh[t] = local;
    __syncthreads();
    for (int ofs = 1; ofs < 256; ofs <<= 1) {
        int val = 0;
        if (t >= ofs) val = sh[t - ofs];
        __syncthreads();
        sh[t] += val;
        __syncthreads();
    }
    int excl = sh[t] - local + bpre;
    #pragma unroll
    for (int i = 0; i < 4; i++) {
        int v = base + i;
        if (v < V) { g_off[v] = excl; g_cur[v] = excl; }
        excl += c[i];
    }
}

// ---------------- launch 5: scatter into CSR ---------------------------------
__global__ void k_scatter(const int* __restrict__ dst,
                          const int* __restrict__ et,
                          const float* __restrict__ norm) {
    int i = blockIdx.x * blockDim.x + threadIdx.x;
    if (i < E) {
        int v = dst[i];
        int p = atomicAdd(&g_cur[v], 1);
        uint2 rec;
        rec.x = (unsigned)et[i] + ((i >= HALF) ? R : 0);
        rec.y = __float_as_uint(norm[i]);
        g_edge[p] = rec;
    }
}

// ---------------- launch 6: edge aggregation + stats, RMW into out -----------
__global__ void __launch_bounds__(448) k_edge(float* __restrict__ out) {
    int t = threadIdx.x;
    int g = t / 224, o = t % 224;
    int v0 = blockIdx.x * 16 + g * 8;
    if (o < D) {
        float lsum = 0.f, lsq = 0.f;
        #pragma unroll 1
        for (int n = 0; n < 8; n++) {
            int vtx = v0 + n;
            int e  = g_off[vtx];
            int t2 = g_off[vtx + 1];
            float a = 0.f;
            for (; e + 4 <= t2; e += 4) {
                uint2 r0 = g_edge[e],     r1 = g_edge[e + 1];
                uint2 r2 = g_edge[e + 2], r3 = g_edge[e + 3];
                float m0 = g_Mtab[(int)r0.x * D + o];
                float m1 = g_Mtab[(int)r1.x * D + o];
                float m2 = g_Mtab[(int)r2.x * D + o];
                float m3 = g_Mtab[(int)r3.x * D + o];
                a += __uint_as_float(r0.y) * m0 + __uint_as_float(r1.y) * m1;
                a += __uint_as_float(r2.y) * m2 + __uint_as_float(r3.y) * m3;
            }
            for (; e < t2; e++) {
                uint2 r = g_edge[e];
                a += __uint_as_float(r.y) * g_Mtab[(int)r.x * D + o];
            }
            size_t idx = (size_t)vtx * D + o;
            float p = out[idx] + a;
            out[idx] = p;
            lsum += p;
            lsq  += p * p;
        }
        atomicAdd(&g_stats[o], lsum);
        atomicAdd(&g_stats[D + o], lsq);
    }
}

// ---------------- launch 7: BN finalize + normalize --------------------------
__global__ void k_norm(const float* __restrict__ bnw,
                       const float* __restrict__ bnb,
                       float* __restrict__ out) {
    __shared__ float sc[D], sh[D];
    int t = threadIdx.x;
    for (int i = t; i < D; i += blockDim.x) {
        float mean = g_stats[i] * (1.f / (float)V);
        float var  = g_stats[D + i] * (1.f / (float)V) - mean * mean;
        float s    = bnw[i] * rsqrtf(var + 1e-5f);
        sc[i] = s;
        sh[i] = bnb[i] - mean * s;
    }
    __syncthreads();
    const int n4 = V * D / 4;
    for (int i = blockIdx.x * blockDim.x + t; i < n4; i += gridDim.x * blockDim.x) {
        float4 v = ((float4*)out)[i];
        int o = (i * 4) % D;
        v.x = v.x * sc[o]     + sh[o];
        v.y = v.y * sc[o + 1] + sh[o + 1];
        v.z = v.z * sc[o + 2] + sh[o + 2];
        v.w = v.w * sc[o + 3] + sh[o + 3];
        ((float4*)out)[i] = v;
    }
}

// ---------------- launch ----------------------------------------------------
extern "C" void kernel_launch(void* const* d_in, const int* in_sizes, int n_in,
                              void* d_out, int out_size) {
    const float* x        = (const float*)d_in[0];
    const float* rel      = (const float*)d_in[1];
    const float* enorm    = (const float*)d_in[2];
    const float* in_w     = (const float*)d_in[3];
    const float* out_w    = (const float*)d_in[4];
    const float* loop_w   = (const float*)d_in[5];
    const float* w_rel    = (const float*)d_in[6];
    const float* loop_rel = (const float*)d_in[7];
    const float* bias     = (const float*)d_in[8];
    const float* bnw      = (const float*)d_in[9];
    const float* bnb      = (const float*)d_in[10];
    const int*   et       = (const int*)d_in[11];
    const int*   dst      = (const int*)d_in[12];
    float*       out      = (float*)d_out;

    k_pre<<<2 * R + D + R + NBLK + 1, 256>>>(rel, in_w, out_w, loop_rel,
                                             loop_w, w_rel,
                                             out + (size_t)V * D);       // 0
    k_hist<<<(E + 255) / 256, 256>>>(dst);                               // 1
    k_scan1<<<NBLK, 256>>>();                                            // 2
    k_gemm<<<NGB, 160>>>(x, bias, out);                                  // 3 <- ncu
    k_scan3m<<<NBLK, 256>>>();                                           // 4
    k_scatter<<<(E + 255) / 256, 256>>>(dst, et, enorm);                 // 5
    k_edge<<<V / 16, 448>>>(out);                                        // 6
    k_norm<<<2048, 256>>>(bnw, bnb, out);                                // 7
}